// round 16
// baseline (speedup 1.0000x reference)
#include <cuda_runtime.h>
#include <cuda_bf16.h>

// y[b,c,h,w] = coef[c] * g[b,c,h,w]
// g: (32, 512, 64, 64) fp32, coef: (512,) fp32.
//
// FINAL — best of 9 measured variants (harness 81.92us / 81.95us across two
// independent runs; ncu 73.3-74.7us, DRAM 81.5-83.0%, 6.5+ TB/s):
//   - one block = 256 threads x 4 float4 = one 4096-float (b,c) channel
//     plane; grid = 16384; coef index block-uniform (c = blockIdx.x & 511)
//   - ILP=4 front-batched LDG.128.cs (MLP=4 outstanding loads/thread),
//     FMULs, then 4x STG.128.cs
//   - .cs (evict-first) on BOTH loads and stores: measured optimum.
// Ruled out by measurement: MLP=8 (reg pressure/occupancy), 256-bit
// accesses, persistent grid-stride (loop-carried MLP throttle, -12%),
// 512-thread/2-plane blocks, interleaved store scheduling, write-through
// stores (-0.7us, loses L2 store combining). Harness steady-state is pinned
// at ~6.5 TB/s sustained by DVFS under continuous HBM load; this config
// sits on that floor with minimal possible traffic (512 MiB R+W).

__global__ __launch_bounds__(256)
void Gradient_28733331210651_kernel(const float4* __restrict__ g4,
                                    const float* __restrict__ coef,
                                    float4* __restrict__ out4) {
    // Block-uniform channel + scale
    const int c = blockIdx.x & 511;
    const float s = __ldg(coef + c);

    const long long base = (long long)blockIdx.x * 1024 + threadIdx.x;

    // Front-batched streaming loads (MLP=4)
    float4 v0 = __ldcs(g4 + base);
    float4 v1 = __ldcs(g4 + base + 256);
    float4 v2 = __ldcs(g4 + base + 512);
    float4 v3 = __ldcs(g4 + base + 768);

    v0.x *= s; v0.y *= s; v0.z *= s; v0.w *= s;
    v1.x *= s; v1.y *= s; v1.z *= s; v1.w *= s;
    v2.x *= s; v2.y *= s; v2.z *= s; v2.w *= s;
    v3.x *= s; v3.y *= s; v3.z *= s; v3.w *= s;

    __stcs(out4 + base,       v0);
    __stcs(out4 + base + 256, v1);
    __stcs(out4 + base + 512, v2);
    __stcs(out4 + base + 768, v3);
}

extern "C" void kernel_launch(void* const* d_in, const int* in_sizes, int n_in,
                              void* d_out, int out_size) {
    const float4* g4   = (const float4*)d_in[0];
    const float*  coef = (const float*)d_in[1];
    float4*       out4 = (float4*)d_out;

    // 32*512*64*64 floats; one block per 4096-float channel plane
    long long n  = (long long)in_sizes[0];      // 67108864
    long long blocks = n >> 12;                 // 16384

    Gradient_28733331210651_kernel<<<(unsigned)blocks, 256>>>(g4, coef, out4);
}

// round 17
// speedup vs baseline: 1.0078x; 1.0078x over previous
#include <cuda_runtime.h>
#include <cuda_bf16.h>

// y[b,c,h,w] = coef[c] * g[b,c,h,w]
// g: (32, 512, 64, 64) fp32, coef: (512,) fp32.
//
// FINAL — best measured config, held. Identical-source runs measured
// 81.92 / 81.95 / 82.66 us (harness) and 73.3-79.6 us (single-launch ncu),
// establishing a ~0.7 us harness noise band; all nine measured variants
// (MLP 1/4/8, 128/256-bit, persistent, 512-thread, interleaved stores,
// .wt stores) fall on the same ~6.5 TB/s sustained-bandwidth floor except
// the persistent grid-stride which regressed 12%.
//
// Config:
//   - one block = 256 threads x 4 float4 = one 4096-float (b,c) channel
//     plane; grid = 16384; coef index block-uniform (c = blockIdx.x & 511)
//   - ILP=4 front-batched LDG.128.cs (MLP=4 outstanding loads/thread),
//     FMULs, then 4x STG.128.cs
//   - .cs (evict-first) on both loads and stores (zero-reuse 512 MiB stream)

__global__ __launch_bounds__(256)
void Gradient_28733331210651_kernel(const float4* __restrict__ g4,
                                    const float* __restrict__ coef,
                                    float4* __restrict__ out4) {
    // Block-uniform channel + scale
    const int c = blockIdx.x & 511;
    const float s = __ldg(coef + c);

    const long long base = (long long)blockIdx.x * 1024 + threadIdx.x;

    // Front-batched streaming loads (MLP=4)
    float4 v0 = __ldcs(g4 + base);
    float4 v1 = __ldcs(g4 + base + 256);
    float4 v2 = __ldcs(g4 + base + 512);
    float4 v3 = __ldcs(g4 + base + 768);

    v0.x *= s; v0.y *= s; v0.z *= s; v0.w *= s;
    v1.x *= s; v1.y *= s; v1.z *= s; v1.w *= s;
    v2.x *= s; v2.y *= s; v2.z *= s; v2.w *= s;
    v3.x *= s; v3.y *= s; v3.z *= s; v3.w *= s;

    __stcs(out4 + base,       v0);
    __stcs(out4 + base + 256, v1);
    __stcs(out4 + base + 512, v2);
    __stcs(out4 + base + 768, v3);
}

extern "C" void kernel_launch(void* const* d_in, const int* in_sizes, int n_in,
                              void* d_out, int out_size) {
    const float4* g4   = (const float4*)d_in[0];
    const float*  coef = (const float*)d_in[1];
    float4*       out4 = (float4*)d_out;

    // 32*512*64*64 floats; one block per 4096-float channel plane
    long long n  = (long long)in_sizes[0];      // 67108864
    long long blocks = n >> 12;                 // 16384

    Gradient_28733331210651_kernel<<<(unsigned)blocks, 256>>>(g4, coef, out4);
}